// round 16
// baseline (speedup 1.0000x reference)
#include <cuda_runtime.h>

// Problem constants (fixed shapes from reference setup_inputs)
#define BB   2
#define CC   32
#define HH   47
#define WW   156
#define DD   120
#define DP1  121              // D+1 softmax channels
#define HW   (HH * WW)        // 7332
#define QW   (HW / 4)         // 1833 float4s per (h,w) plane
#define NPIX (BB * HW)        // 14664
#define NFF  (BB * CC * DD * HW)  // 56,309,760 elements per frustum tensor
#define HP   (HH * 8)         // 376
#define WP   (WW * 8)         // 1248
#define DQ   (DD / 4)         // 30 d-slabs of 4
#define CG   4                // c-groups: wall-limited best config
#define CPG  (CC / CG)        // 8 channels per group

// Single-kernel grid layout: [denom | frustum | pool]
#define DENOM_BLOCKS ((NPIX + 31) / 32)                 // 459 (32 px/block)
#define FRUST_BLOCKS ((BB * CG * DQ * QW + 255) / 256)  // 1719
#define POOL_BLOCKS  ((NPIX + 255) / 256)               // 58
#define ALL_BLOCKS   (DENOM_BLOCKS + FRUST_BLOCKS + POOL_BLOCKS)  // 2236

// Scratch: per-pixel inverse softmax denominators + decoupled-flag counters.
__device__ float g_inv[NPIX];
__device__ volatile int g_done;      // denom blocks completed (self-resets)
__device__ int          g_consumed;  // frustum blocks past the wait

// ---------------------------------------------------------------------------
// Single fused kernel (round-15 structure). One change: the img tile iv[8]
// is loaded ONCE in pass 1 and kept live in registers across the wait for
// reuse in pass 2, removing 16 redundant L1/L2 load wavefronts per thread
// (L1 was the nearest-to-ceiling unit at 66.9%). Occupancy drops to
// ~3 blocks/SM, which rounds 6/9/10 proved is not the binding constraint.
// ---------------------------------------------------------------------------
__global__ void __launch_bounds__(256) fused_kernel(
    const float* __restrict__ logits,
    const float* __restrict__ img,
    const int*   __restrict__ bins,
    const float* __restrict__ dm,
    float*       __restrict__ out)
{
    int t = threadIdx.x;

    if (blockIdx.x < DENOM_BLOCKS) {
        // ---------------- softmax denominators ----------------
        __shared__ float part[32][8];
        int pl = t & 31;           // pixel within block
        int q  = t >> 5;           // channel-chunk 0..7 (16 channels each)
        int p  = blockIdx.x * 32 + pl;

        float s = 0.f;
        if (p < NPIX) {
            int b   = p / HW;
            int rem = p - b * HW;
            const float* base = logits + (size_t)b * DP1 * HW + rem;
            int c0 = q * 16;
            int c1 = c0 + 16; if (c1 > DP1) c1 = DP1;   // q==7: 112..120
            #pragma unroll
            for (int ch = 0; ch < 16; ch++) {
                if (c0 + ch < c1)
                    s += __expf(base[(size_t)(c0 + ch) * HW]);
            }
        }
        part[pl][q] = s;
        __syncthreads();
        if (q == 0 && p < NPIX) {
            float tot = 0.f;
            #pragma unroll
            for (int i = 0; i < 8; i++) tot += part[pl][i];
            g_inv[p] = 1.0f / tot;
            __threadfence();       // make g_inv visible device-wide
        }
        __syncthreads();
        if (t == 0)
            atomicAdd((int*)&g_done, 1);
        return;
    }

    if (blockIdx.x >= DENOM_BLOCKS + FRUST_BLOCKS) {
        // ---------------- sparse 8x8 average pool (independent) ----------------
        int p = (blockIdx.x - DENOM_BLOCKS - FRUST_BLOCKS) * 256 + t;
        if (p >= NPIX) return;
        int b   = p / HW;
        int rem = p - b * HW;
        int h   = rem / WW;
        int w   = rem - h * WW;

        const float* base = dm + ((size_t)b * HP + (size_t)h * 8) * WP + (size_t)w * 8;

        float sum = 0.f;
        float cnt = 0.f;
        #pragma unroll
        for (int i = 0; i < 8; i++) {
            const float4* row = reinterpret_cast<const float4*>(base + (size_t)i * WP);
            float4 v0 = row[0];
            float4 v1 = row[1];
            sum += (v0.x + v0.y) + (v0.z + v0.w) + (v1.x + v1.y) + (v1.z + v1.w);
            cnt += (v0.x != 0.f) + (v0.y != 0.f) + (v0.z != 0.f) + (v0.w != 0.f)
                 + (v1.x != 0.f) + (v1.y != 0.f) + (v1.z != 0.f) + (v1.w != 0.f);
        }
        float a  = sum * (1.0f / 64.0f);
        float bf = cnt * (1.0f / 64.0f);
        out[2 * (size_t)NFF + p] = a / (bf + 1e-10f);
        return;
    }

    // ---------------- frustum writer (two-pass) ----------------
    unsigned idx = (blockIdx.x - DENOM_BLOCKS) * blockDim.x + t;
    unsigned p4 = idx % QW;
    unsigned r  = idx / QW;
    unsigned dq = r % DQ;
    r /= DQ;
    unsigned cg = r % CG;
    unsigned b  = r / CG;
    bool valid = (b < BB);

    int d0 = dq * 4;
    int c0 = cg * CPG;

    const float4* ig = (const float4*)img + ((size_t)b * CC + c0) * QW + p4;
    float4* ob = (float4*)out + (((size_t)b * CC + c0) * DD + d0) * QW + p4;
    const size_t cstride = (size_t)DD * QW;
    const size_t osplit  = (size_t)NFF / 4;

    // ---- img tile: loaded once, lives across the wait ----
    float4 iv[CPG];
    if (valid) {
        #pragma unroll
        for (int c = 0; c < CPG; c++)
            iv[c] = ig[(size_t)c * QW];
    }

    // ---- Pass 1: target tensor (no g_inv dependency) ----
    if (valid) {
        int4 bn = ((const int4*)bins)[(size_t)b * QW + p4];
        #pragma unroll
        for (int c = 0; c < CPG; c++) {
            float4* o2 = ob + (size_t)c * cstride + osplit;
            #pragma unroll
            for (int j = 0; j < 4; j++) {
                int d = d0 + j;
                float4 tg;
                tg.x = (d == bn.x) ? iv[c].x : 0.0f;
                tg.y = (d == bn.y) ? iv[c].y : 0.0f;
                tg.z = (d == bn.z) ? iv[c].z : 0.0f;
                tg.w = (d == bn.w) ? iv[c].w : 0.0f;
                __stcs(&o2[(size_t)j * QW], tg);
            }
        }
    }

    // ---- Wait for denom blocks (fully hidden under pass-1 stores) ----
    if (t == 0) {
        while (g_done < DENOM_BLOCKS) { __nanosleep(64); }
        __threadfence();   // acquire: g_inv writes now visible
    }
    __syncthreads();

    // ---- Pass 2: softmax-apply + frustum_features ----
    if (valid) {
        float4 I = ((const float4*)g_inv)[(size_t)b * QW + p4];
        float4 P[4];
        #pragma unroll
        for (int j = 0; j < 4; j++) {
            float4 L = ((const float4*)logits)[((size_t)b * DP1 + d0 + j) * QW + p4];
            P[j].x = __expf(L.x) * I.x;
            P[j].y = __expf(L.y) * I.y;
            P[j].z = __expf(L.z) * I.z;
            P[j].w = __expf(L.w) * I.w;
        }

        #pragma unroll
        for (int c = 0; c < CPG; c++) {
            float4* o1 = ob + (size_t)c * cstride;
            #pragma unroll
            for (int j = 0; j < 4; j++) {
                float4 a;
                a.x = iv[c].x * P[j].x; a.y = iv[c].y * P[j].y;
                a.z = iv[c].z * P[j].z; a.w = iv[c].w * P[j].w;
                __stcs(&o1[(size_t)j * QW], a);
            }
        }
    }

    // ---- Counter self-reset so graph replays start clean ----
    if (t == 0) {
        int old = atomicAdd(&g_consumed, 1);
        if (old == FRUST_BLOCKS - 1) {   // last frustum block past the wait
            g_done = 0;
            g_consumed = 0;
        }
    }
}

// ---------------------------------------------------------------------------
// Launch contract
// Inputs: image_features f32, depth_logits f32, depth_maps f32,
//         depth_target_bin i32
// Output: [frustum_features | frustum_features_target | pooled_depth] f32
// ---------------------------------------------------------------------------
extern "C" void kernel_launch(void* const* d_in, const int* in_sizes, int n_in,
                              void* d_out, int out_size) {
    const float* image_features   = (const float*)d_in[0];
    const float* depth_logits     = (const float*)d_in[1];
    const float* depth_maps       = (const float*)d_in[2];
    const int*   depth_target_bin = (const int*)d_in[3];
    float* out = (float*)d_out;

    fused_kernel<<<ALL_BLOCKS, 256>>>(depth_logits, image_features,
                                      depth_target_bin, depth_maps, out);
}

// round 17
// speedup vs baseline: 1.0241x; 1.0241x over previous
#include <cuda_runtime.h>

// Problem constants (fixed shapes from reference setup_inputs)
#define BB   2
#define CC   32
#define HH   47
#define WW   156
#define DD   120
#define DP1  121              // D+1 softmax channels
#define HW   (HH * WW)        // 7332
#define QW   (HW / 4)         // 1833 float4s per (h,w) plane
#define NPIX (BB * HW)        // 14664
#define NFF  (BB * CC * DD * HW)  // 56,309,760 elements per frustum tensor
#define HP   (HH * 8)         // 376
#define WP   (WW * 8)         // 1248
#define DQ   (DD / 4)         // 30 d-slabs of 4
#define CG   4                // c-groups: wall-limited best config
#define CPG  (CC / CG)        // 8 channels per group

// Single-kernel grid layout: [denom | frustum | pool]
#define DENOM_BLOCKS ((NPIX + 31) / 32)                 // 459 (32 px/block)
#define FRUST_BLOCKS ((BB * CG * DQ * QW + 255) / 256)  // 1719
#define POOL_BLOCKS  ((NPIX + 255) / 256)               // 58
#define ALL_BLOCKS   (DENOM_BLOCKS + FRUST_BLOCKS + POOL_BLOCKS)  // 2236

// Scratch: per-pixel inverse softmax denominators + decoupled-flag counters.
__device__ float g_inv[NPIX];
__device__ volatile int g_done;      // denom blocks completed (self-resets)
__device__ int          g_consumed;  // frustum blocks past the wait

// ---------------------------------------------------------------------------
// Single fused kernel (round-15 structure — measured optimum, 78.4us).
// Block role by blockIdx.x:
//  [0, DENOM): softmax denominators -> g_inv, then signal g_done.
//     All 459 denom blocks fit in scheduling wave 1 and are dispatched
//     first => signal always arrives; no deadlock.
//  [DENOM, DENOM+FRUST): two-pass frustum writer. Pass 1 = target-tensor
//     stores (no g_inv needed, ~40us overlap budget hides denom's ~3us).
//     Then thread 0 spins on g_done, barrier, pass 2 = softmax-apply +
//     frustum_features stores. img tile deliberately RE-LOADED in pass 2:
//     keeping it in registers (r16) cost 90 regs -> occ 22.6% -> +5us.
//     46 regs / 56% occ sits on the flat part of the occupancy curve.
//  [DENOM+FRUST, ...): independent sparse 8x8 pool.
// Counters self-reset (last frustum block) so graph replays start clean.
// ---------------------------------------------------------------------------
__global__ void __launch_bounds__(256) fused_kernel(
    const float* __restrict__ logits,
    const float* __restrict__ img,
    const int*   __restrict__ bins,
    const float* __restrict__ dm,
    float*       __restrict__ out)
{
    int t = threadIdx.x;

    if (blockIdx.x < DENOM_BLOCKS) {
        // ---------------- softmax denominators ----------------
        __shared__ float part[32][8];
        int pl = t & 31;           // pixel within block
        int q  = t >> 5;           // channel-chunk 0..7 (16 channels each)
        int p  = blockIdx.x * 32 + pl;

        float s = 0.f;
        if (p < NPIX) {
            int b   = p / HW;
            int rem = p - b * HW;
            const float* base = logits + (size_t)b * DP1 * HW + rem;
            int c0 = q * 16;
            int c1 = c0 + 16; if (c1 > DP1) c1 = DP1;   // q==7: 112..120
            #pragma unroll
            for (int ch = 0; ch < 16; ch++) {
                if (c0 + ch < c1)
                    s += __expf(base[(size_t)(c0 + ch) * HW]);
            }
        }
        part[pl][q] = s;
        __syncthreads();
        if (q == 0 && p < NPIX) {
            float tot = 0.f;
            #pragma unroll
            for (int i = 0; i < 8; i++) tot += part[pl][i];
            g_inv[p] = 1.0f / tot;
            __threadfence();       // make g_inv visible device-wide
        }
        __syncthreads();
        if (t == 0)
            atomicAdd((int*)&g_done, 1);
        return;
    }

    if (blockIdx.x >= DENOM_BLOCKS + FRUST_BLOCKS) {
        // ---------------- sparse 8x8 average pool (independent) ----------------
        int p = (blockIdx.x - DENOM_BLOCKS - FRUST_BLOCKS) * 256 + t;
        if (p >= NPIX) return;
        int b   = p / HW;
        int rem = p - b * HW;
        int h   = rem / WW;
        int w   = rem - h * WW;

        const float* base = dm + ((size_t)b * HP + (size_t)h * 8) * WP + (size_t)w * 8;

        float sum = 0.f;
        float cnt = 0.f;
        #pragma unroll
        for (int i = 0; i < 8; i++) {
            const float4* row = reinterpret_cast<const float4*>(base + (size_t)i * WP);
            float4 v0 = row[0];
            float4 v1 = row[1];
            sum += (v0.x + v0.y) + (v0.z + v0.w) + (v1.x + v1.y) + (v1.z + v1.w);
            cnt += (v0.x != 0.f) + (v0.y != 0.f) + (v0.z != 0.f) + (v0.w != 0.f)
                 + (v1.x != 0.f) + (v1.y != 0.f) + (v1.z != 0.f) + (v1.w != 0.f);
        }
        float a  = sum * (1.0f / 64.0f);
        float bf = cnt * (1.0f / 64.0f);
        out[2 * (size_t)NFF + p] = a / (bf + 1e-10f);
        return;
    }

    // ---------------- frustum writer (two-pass) ----------------
    unsigned idx = (blockIdx.x - DENOM_BLOCKS) * blockDim.x + t;
    unsigned p4 = idx % QW;
    unsigned r  = idx / QW;
    unsigned dq = r % DQ;
    r /= DQ;
    unsigned cg = r % CG;
    unsigned b  = r / CG;
    bool valid = (b < BB);

    int d0 = dq * 4;
    int c0 = cg * CPG;

    const float4* ig = (const float4*)img + ((size_t)b * CC + c0) * QW + p4;
    float4* ob = (float4*)out + (((size_t)b * CC + c0) * DD + d0) * QW + p4;
    const size_t cstride = (size_t)DD * QW;
    const size_t osplit  = (size_t)NFF / 4;

    // ---- Pass 1: target tensor (no g_inv dependency) ----
    if (valid) {
        int4 bn = ((const int4*)bins)[(size_t)b * QW + p4];
        #pragma unroll 2
        for (int c = 0; c < CPG; c++) {
            float4 iv = ig[(size_t)c * QW];
            float4* o2 = ob + (size_t)c * cstride + osplit;
            #pragma unroll
            for (int j = 0; j < 4; j++) {
                int d = d0 + j;
                float4 tg;
                tg.x = (d == bn.x) ? iv.x : 0.0f;
                tg.y = (d == bn.y) ? iv.y : 0.0f;
                tg.z = (d == bn.z) ? iv.z : 0.0f;
                tg.w = (d == bn.w) ? iv.w : 0.0f;
                __stcs(&o2[(size_t)j * QW], tg);
            }
        }
    }

    // ---- Wait for denom blocks (fully hidden under pass-1 stores) ----
    if (t == 0) {
        while (g_done < DENOM_BLOCKS) { __nanosleep(64); }
        __threadfence();   // acquire: g_inv writes now visible
    }
    __syncthreads();

    // ---- Pass 2: softmax-apply + frustum_features ----
    if (valid) {
        float4 I = ((const float4*)g_inv)[(size_t)b * QW + p4];
        float4 P[4];
        #pragma unroll
        for (int j = 0; j < 4; j++) {
            float4 L = ((const float4*)logits)[((size_t)b * DP1 + d0 + j) * QW + p4];
            P[j].x = __expf(L.x) * I.x;
            P[j].y = __expf(L.y) * I.y;
            P[j].z = __expf(L.z) * I.z;
            P[j].w = __expf(L.w) * I.w;
        }

        #pragma unroll 2
        for (int c = 0; c < CPG; c++) {
            float4 iv = ig[(size_t)c * QW];
            float4* o1 = ob + (size_t)c * cstride;
            #pragma unroll
            for (int j = 0; j < 4; j++) {
                float4 a;
                a.x = iv.x * P[j].x; a.y = iv.y * P[j].y;
                a.z = iv.z * P[j].z; a.w = iv.w * P[j].w;
                __stcs(&o1[(size_t)j * QW], a);
            }
        }
    }

    // ---- Counter self-reset so graph replays start clean ----
    if (t == 0) {
        int old = atomicAdd(&g_consumed, 1);
        if (old == FRUST_BLOCKS - 1) {   // last frustum block past the wait
            g_done = 0;
            g_consumed = 0;
        }
    }
}

// ---------------------------------------------------------------------------
// Launch contract
// Inputs: image_features f32, depth_logits f32, depth_maps f32,
//         depth_target_bin i32
// Output: [frustum_features | frustum_features_target | pooled_depth] f32
// ---------------------------------------------------------------------------
extern "C" void kernel_launch(void* const* d_in, const int* in_sizes, int n_in,
                              void* d_out, int out_size) {
    const float* image_features   = (const float*)d_in[0];
    const float* depth_logits     = (const float*)d_in[1];
    const float* depth_maps       = (const float*)d_in[2];
    const int*   depth_target_bin = (const int*)d_in[3];
    float* out = (float*)d_out;

    fused_kernel<<<ALL_BLOCKS, 256>>>(depth_logits, image_features,
                                      depth_target_bin, depth_maps, out);
}